// round 14
// baseline (speedup 1.0000x reference)
#include <cuda_runtime.h>

#define D_DIM   256
#define K_CENT  1024
#define N_MAX   131072
#define MARGIN  0.1f

__device__ float g_cnorm[K_CENT];
__device__ int   g_amb[N_MAX];
__device__ int   g_count;
__device__ __align__(16) signed char g_xq1[(size_t)N_MAX * D_DIM];  // 32 MB
__device__ __align__(16) signed char g_xq2[(size_t)N_MAX * D_DIM];  // 32 MB
__device__ __align__(16) signed char g_cq1[K_CENT * D_DIM];
__device__ __align__(16) signed char g_cq2[K_CENT * D_DIM];

__global__ void zero_kernel() { if (threadIdx.x == 0) g_count = 0; }

__device__ __forceinline__ int q8(float v, float s) {
    float t = v * s;
    t = fminf(fmaxf(t, -127.f), 127.f);
    return __float2int_rn(t);
}

// x: int8 2-plane quantization (q1 = round(16x), q2 = round(4096*(x-q1/16))).
__global__ void convx_kernel(const float* __restrict__ x) {
    const int t  = threadIdx.x & 127;
    const int rs = threadIdx.x >> 7;
    const size_t row = (size_t)blockIdx.x * 4 + rs;
    float2 v = ((const float2*)(x + row * D_DIM))[t];
    int a1 = q8(v.x, 16.f), b1 = q8(v.y, 16.f);
    int a2 = q8(v.x - a1 * 0.0625f, 4096.f);
    int b2 = q8(v.y - b1 * 0.0625f, 4096.f);
    ((unsigned short*)g_xq1)[row * 128 + t] =
        (unsigned short)((a1 & 0xff) | ((b1 & 0xff) << 8));
    ((unsigned short*)g_xq2)[row * 128 + t] =
        (unsigned short)((a2 & 0xff) | ((b2 & 0xff) << 8));
}

// c: quantization + XLA-order |c|^2 (bit-exact R8 chain).
__global__ void convc_kernel(const float* __restrict__ c) {
    __shared__ float s4[4][4];
    const int t  = threadIdx.x & 127;
    const int rs = threadIdx.x >> 7;
    const int row = blockIdx.x * 4 + rs;
    float2 v = ((const float2*)(c + (size_t)row * D_DIM))[t];
    int a1 = q8(v.x, 16.f), b1 = q8(v.y, 16.f);
    int a2 = q8(v.x - a1 * 0.0625f, 4096.f);
    int b2 = q8(v.y - b1 * 0.0625f, 4096.f);
    ((unsigned short*)g_cq1)[row * 128 + t] =
        (unsigned short)((a1 & 0xff) | ((b1 & 0xff) << 8));
    ((unsigned short*)g_cq2)[row * 128 + t] =
        (unsigned short)((a2 & 0xff) | ((b2 & 0xff) << 8));
    float p = __fmul_rn(v.x, v.x);
    p = __fadd_rn(p, __fmul_rn(v.y, v.y));
#pragma unroll
    for (int off = 16; off; off >>= 1)
        p = __fadd_rn(p, __shfl_down_sync(0xffffffffu, p, off));
    if ((t & 31) == 0) s4[rs][t >> 5] = p;
    __syncthreads();
    if (t == 0)
        g_cnorm[row] = __fadd_rn(__fadd_rn(s4[rs][0], s4[rs][2]),
                                 __fadd_rn(s4[rs][1], s4[rs][3]));
}

__device__ __forceinline__ void top2_update(float& v1, float& v2, int& i1,
                                            float s, int n) {
    if (s < v1)      { v2 = v1; v1 = s; i1 = n; }
    else if (s < v2) { v2 = s; }
}

#define LDSM_X4(R, addr) \
    asm volatile("ldmatrix.sync.aligned.m8n8.x4.shared.b16 {%0,%1,%2,%3}, [%4];" \
        : "=r"((R)[0]), "=r"((R)[1]), "=r"((R)[2]), "=r"((R)[3]) : "r"(addr))

#define IMMA(A, B0, B1, C) \
    asm volatile("mma.sync.aligned.m16n8k32.row.col.s32.s8.s8.s32 " \
        "{%0,%1,%2,%3}, {%4,%5,%6,%7}, {%8,%9}, {%0,%1,%2,%3};" \
        : "+r"((C)[0]), "+r"((C)[1]), "+r"((C)[2]), "+r"((C)[3]) \
        : "r"((A)[0]), "r"((A)[1]), "r"((A)[2]), "r"((A)[3]), "r"(B0), "r"(B1))

// Pass 1: int8 3-term (hh + cross) m16n8k32 MMA GEMM; score = -2*dot + cn.
// CTA: 128 x-rows x 1024 centroids; warp tile m32 x n64 (8 warps, 4m x 2n).
// smem planes (int8, row stride 80B): xq1@0, xq2@10240, cq1@20480, cq2@30720.
__global__ void __launch_bounds__(256, 1)
vq_pass1(const float* __restrict__ c, float* __restrict__ out)
{
    extern __shared__ char smem[];
    float* cns = (float*)(smem + 40960);   // 1024 f32
    int*   si  = (int*)(smem + 45056);     // 128 int
    float* rv1 = (float*)(smem);           // post-loop aliases
    float* rv2 = (float*)(smem + 1024);
    int*   ri1 = (int*)(smem + 2048);

    const int tid  = threadIdx.x;
    const int lane = tid & 31, warp = tid >> 5;
    const int warp_m = warp & 3, warp_n = warp >> 2;
    const int wm0 = warp_m * 32, wn0 = warp_n * 64;
    const int lrow = lane >> 2, kp = (lane & 3) * 2;
    const long long m0 = (long long)blockIdx.x * 128;

    for (int i = tid; i < K_CENT; i += 256) cns[i] = g_cnorm[i];

    const unsigned sb = (unsigned)__cvta_generic_to_shared(smem);
    unsigned aAddr[2], bAddr[4];
#pragma unroll
    for (int mi = 0; mi < 2; ++mi)
        aAddr[mi] = sb + (wm0 + mi * 16 + (lane & 15)) * 80 + (lane >> 4) * 16;
#pragma unroll
    for (int q = 0; q < 4; ++q)
        bAddr[q] = sb + 20480 + (wn0 + q * 16 + (lane & 15)) * 80 + (lane >> 4) * 16;

    float v1[4], v2[4]; int i1[4];
#pragma unroll
    for (int r = 0; r < 4; ++r) { v1[r] = 3.4e38f; v2[r] = 3.4e38f; i1[r] = 0; }

    for (int n0t = 0; n0t < 8; ++n0t) {
        const int n0 = n0t * 128;
        int hh[2][8][4], cr[2][8][4];
#pragma unroll
        for (int mi = 0; mi < 2; ++mi)
#pragma unroll
            for (int ni = 0; ni < 8; ++ni)
#pragma unroll
                for (int j = 0; j < 4; ++j) { hh[mi][ni][j] = 0; cr[mi][ni][j] = 0; }

        for (int k0 = 0; k0 < D_DIM; k0 += 64) {
            __syncthreads();
            // stage 4 planes: 128 rows x 64 int8 each = 512 uint4
#pragma unroll
            for (int it = 0; it < 2; ++it) {
                int idx = it * 256 + tid;
                int m = idx >> 2, u = idx & 3;
                *(uint4*)(smem + m * 80 + u * 16) =
                    *(const uint4*)(g_xq1 + (m0 + m) * D_DIM + k0 + u * 16);
                *(uint4*)(smem + 10240 + m * 80 + u * 16) =
                    *(const uint4*)(g_xq2 + (m0 + m) * D_DIM + k0 + u * 16);
                *(uint4*)(smem + 20480 + m * 80 + u * 16) =
                    *(const uint4*)(g_cq1 + (size_t)(n0 + m) * D_DIM + k0 + u * 16);
                *(uint4*)(smem + 30720 + m * 80 + u * 16) =
                    *(const uint4*)(g_cq2 + (size_t)(n0 + m) * D_DIM + k0 + u * 16);
            }
            __syncthreads();

#pragma unroll
            for (int kk = 0; kk < 64; kk += 32) {
                unsigned ah[2][4], al[2][4];
#pragma unroll
                for (int mi = 0; mi < 2; ++mi) {
                    LDSM_X4(ah[mi], aAddr[mi] + kk);
                    LDSM_X4(al[mi], aAddr[mi] + 10240 + kk);
                }
                unsigned bh[4][4], bl[4][4];
#pragma unroll
                for (int q = 0; q < 4; ++q) {
                    LDSM_X4(bh[q], bAddr[q] + kk);
                    LDSM_X4(bl[q], bAddr[q] + 10240 + kk);
                }
#pragma unroll
                for (int mi = 0; mi < 2; ++mi)
#pragma unroll
                    for (int q = 0; q < 4; ++q)
#pragma unroll
                        for (int p = 0; p < 2; ++p) {
                            int ni = q * 2 + p;
                            IMMA(ah[mi], bh[q][p], bh[q][p + 2], hh[mi][ni]);
                            IMMA(al[mi], bh[q][p], bh[q][p + 2], cr[mi][ni]);
                            IMMA(ah[mi], bl[q][p], bl[q][p + 2], cr[mi][ni]);
                        }
            }
        }

        // epilogue: dequant + top-2; n ascending per thread
        const float S1 = -2.0f / 256.0f, S2 = -2.0f / 65536.0f;
#pragma unroll
        for (int ni = 0; ni < 8; ++ni) {
            int n = n0 + wn0 + ni * 8 + kp;
            float cn0 = cns[n], cn1 = cns[n + 1];
#pragma unroll
            for (int mi = 0; mi < 2; ++mi) {
                float s0 = fmaf(S1, (float)hh[mi][ni][0],
                                fmaf(S2, (float)cr[mi][ni][0], cn0));
                float s1 = fmaf(S1, (float)hh[mi][ni][1],
                                fmaf(S2, (float)cr[mi][ni][1], cn1));
                float s2 = fmaf(S1, (float)hh[mi][ni][2],
                                fmaf(S2, (float)cr[mi][ni][2], cn0));
                float s3 = fmaf(S1, (float)hh[mi][ni][3],
                                fmaf(S2, (float)cr[mi][ni][3], cn1));
                top2_update(v1[mi*2],   v2[mi*2],   i1[mi*2],   s0, n);
                top2_update(v1[mi*2],   v2[mi*2],   i1[mi*2],   s1, n + 1);
                top2_update(v1[mi*2+1], v2[mi*2+1], i1[mi*2+1], s2, n);
                top2_update(v1[mi*2+1], v2[mi*2+1], i1[mi*2+1], s3, n + 1);
            }
        }
    }

    // quad reduce (lanes 4q..4q+3 share rows)
#pragma unroll
    for (int off = 1; off <= 2; off <<= 1) {
#pragma unroll
        for (int rp = 0; rp < 4; ++rp) {
            float ov1 = __shfl_xor_sync(0xffffffffu, v1[rp], off);
            int   oi1 = __shfl_xor_sync(0xffffffffu, i1[rp], off);
            float ov2 = __shfl_xor_sync(0xffffffffu, v2[rp], off);
            if (ov1 < v1[rp] || (ov1 == v1[rp] && oi1 < i1[rp])) {
                v2[rp] = fminf(v1[rp], ov2);
                v1[rp] = ov1; i1[rp] = oi1;
            } else {
                v2[rp] = fminf(v2[rp], ov1);
            }
        }
    }

    __syncthreads();
    if ((lane & 3) == 0) {
#pragma unroll
        for (int rp = 0; rp < 4; ++rp) {
            int row = wm0 + (rp >> 1) * 16 + (rp & 1) * 8 + lrow;
            rv1[row * 2 + warp_n] = v1[rp];
            rv2[row * 2 + warp_n] = v2[rp];
            ri1[row * 2 + warp_n] = i1[rp];
        }
    }
    __syncthreads();

    if (tid < 128) {
        float a1 = rv1[tid * 2], a2 = rv2[tid * 2];
        int   ai = ri1[tid * 2];
        float b1 = rv1[tid * 2 + 1], b2 = rv2[tid * 2 + 1];
        int   bi = ri1[tid * 2 + 1];
        float fv1, fv2; int fi;
        if (a1 < b1 || (a1 == b1 && ai < bi)) {
            fv1 = a1; fi = ai; fv2 = fminf(a2, b1);
        } else {
            fv1 = b1; fi = bi; fv2 = fminf(b2, a1);
        }
        si[tid] = fi;
        if (fv2 - fv1 < MARGIN) {
            int p = atomicAdd(&g_count, 1);
            g_amb[p] = (int)(m0 + tid);
        }
    }
    __syncthreads();

    {
        int rr = tid >> 1, half = tid & 1;
        int bi = si[rr];
        const float4* src = (const float4*)(c + (size_t)bi * D_DIM) + half * 32;
        float4*       dst = (float4*)(out + (m0 + rr) * D_DIM) + half * 32;
#pragma unroll
        for (int q = 0; q < 32; ++q) dst[q] = src[q];
    }
}

// Rescore: 4 ambiguous rows per block (c tiles shared). Exact R8 chain:
// XLA-order xn; ascending-k=256 single-accumulator FFMA per centroid;
// score fl(fl(-2*dot+xn)+cn); first-index argmin.
__global__ void __launch_bounds__(128)
vq_rescore(const float* __restrict__ x, const float* __restrict__ c,
           float* __restrict__ out)
{
    extern __shared__ float sm[];
    float* xrow = sm;                     // [4][256]
    float* cs   = sm + 1024;              // [64][129]
    float* rv   = sm + 1024 + 8256;       // [128]
    int*   ri   = (int*)(rv + 128);       // [128]
    int*   rows = (int*)(ri + 128);       // [4]
    int*   fi   = rows + 4;               // [4]
    float* xn_s = (float*)(fi + 4);       // [4]
    float* s4   = xn_s + 4;               // [4]

    const int t = threadIdx.x;
    const int count = g_count;
    const int ntiles = (count + 3) >> 2;

    for (int tile = blockIdx.x; tile < ntiles; tile += gridDim.x) {
        if (t < 4) {
            int gi = tile * 4 + t; if (gi > count - 1) gi = count - 1;
            rows[t] = g_amb[gi];
        }
        __syncthreads();

        // stage 4 x rows + XLA-order |x|^2 each
        for (int r = 0; r < 4; ++r) {
            float2 v = ((const float2*)(x + (size_t)rows[r] * D_DIM))[t];
            ((float2*)(xrow + r * 256))[t] = v;
            float p = __fmul_rn(v.x, v.x);
            p = __fadd_rn(p, __fmul_rn(v.y, v.y));
#pragma unroll
            for (int off = 16; off; off >>= 1)
                p = __fadd_rn(p, __shfl_down_sync(0xffffffffu, p, off));
            if ((t & 31) == 0) s4[t >> 5] = p;
            __syncthreads();
            if (t == 0)
                xn_s[r] = __fadd_rn(__fadd_rn(s4[0], s4[2]),
                                    __fadd_rn(s4[1], s4[3]));
            __syncthreads();
        }

        float bestv[4]; int besti[4];
#pragma unroll
        for (int r = 0; r < 4; ++r) { bestv[r] = 3.4e38f; besti[r] = 0; }

        for (int n0 = 0; n0 < K_CENT; n0 += 128) {
            float acc[4] = {0.f, 0.f, 0.f, 0.f};   // thread owns centroid n0+t
            for (int k0 = 0; k0 < D_DIM; k0 += 64) {
                __syncthreads();
#pragma unroll
                for (int it = 0; it < 16; ++it) {
                    int idx = it * 128 + t;
                    int n = idx >> 4, f4 = idx & 15;
                    float4 cv = ((const float4*)(c + (size_t)(n0 + n) * D_DIM + k0))[f4];
                    int kk = f4 * 4;
                    cs[(kk + 0) * 129 + n] = cv.x;
                    cs[(kk + 1) * 129 + n] = cv.y;
                    cs[(kk + 2) * 129 + n] = cv.z;
                    cs[(kk + 3) * 129 + n] = cv.w;
                }
                __syncthreads();
#pragma unroll 8
                for (int k = 0; k < 64; ++k) {
                    float cv = cs[k * 129 + t];
#pragma unroll
                    for (int r = 0; r < 4; ++r)
                        acc[r] = __fmaf_rn(xrow[r * 256 + k0 + k], cv, acc[r]);
                }
            }
            float cn = g_cnorm[n0 + t];
#pragma unroll
            for (int r = 0; r < 4; ++r) {
                float s = __fadd_rn(__fadd_rn(__fmul_rn(-2.0f, acc[r]),
                                              xn_s[r]), cn);
                if (s < bestv[r]) { bestv[r] = s; besti[r] = n0 + t; }
            }
        }

        // per-row tree reduce with first-index tie-break
        for (int r = 0; r < 4; ++r) {
            rv[t] = bestv[r]; ri[t] = besti[r];
            __syncthreads();
            for (int o = 64; o; o >>= 1) {
                if (t < o) {
                    float ov = rv[t + o]; int oi = ri[t + o];
                    if (ov < rv[t] || (ov == rv[t] && oi < ri[t])) {
                        rv[t] = ov; ri[t] = oi;
                    }
                }
                __syncthreads();
            }
            if (t == 0) fi[r] = ri[0];
            __syncthreads();
        }

        // write 4 rows: 256 float4 total, 2 per thread
#pragma unroll
        for (int it = 0; it < 2; ++it) {
            int idx = it * 128 + t;
            int r = idx >> 6, q = idx & 63;
            const float4* src = (const float4*)(c + (size_t)fi[r] * D_DIM);
            float4*       dst = (float4*)(out + (size_t)rows[r] * D_DIM);
            dst[q] = src[q];
        }
        __syncthreads();
    }
}

extern "C" void kernel_launch(void* const* d_in, const int* in_sizes, int n_in,
                              void* d_out, int out_size) {
    const float* x = (const float*)d_in[0];
    const float* c = (const float*)d_in[1];
    float* out = (float*)d_out;
    int N = in_sizes[0] / D_DIM;   // 131072
    int K = in_sizes[1] / D_DIM;   // 1024

    zero_kernel<<<1, 32>>>();
    convx_kernel<<<N / 4, 512>>>(x);
    convc_kernel<<<K / 4, 512>>>(c);
    vq_pass1<<<N / 128, 256, 45568>>>(c, out);
    vq_rescore<<<256, 128, 38400>>>(x, c, out);
}

// round 15
// speedup vs baseline: 1.1114x; 1.1114x over previous
#include <cuda_runtime.h>

#define D_DIM   256
#define K_CENT  1024
#define N_MAX   131072
#define MARGIN  0.1f

__device__ float g_cnorm[K_CENT];
__device__ int   g_amb[N_MAX];
__device__ int   g_count;
__device__ __align__(16) signed char g_xq1[(size_t)N_MAX * D_DIM];  // 32 MB
__device__ __align__(16) signed char g_xq2[(size_t)N_MAX * D_DIM];  // 32 MB
__device__ __align__(16) signed char g_cq1[K_CENT * D_DIM];
__device__ __align__(16) signed char g_cq2[K_CENT * D_DIM];

__global__ void zero_kernel() { if (threadIdx.x == 0) g_count = 0; }

__device__ __forceinline__ int q8(float v, float s) {
    float t = v * s;
    t = fminf(fmaxf(t, -127.f), 127.f);
    return __float2int_rn(t);
}

// x: int8 2-plane quantization (q1 = round(16x), q2 = round(4096*(x-q1/16))).
__global__ void convx_kernel(const float* __restrict__ x) {
    const int t  = threadIdx.x & 127;
    const int rs = threadIdx.x >> 7;
    const size_t row = (size_t)blockIdx.x * 4 + rs;
    float2 v = ((const float2*)(x + row * D_DIM))[t];
    int a1 = q8(v.x, 16.f), b1 = q8(v.y, 16.f);
    int a2 = q8(v.x - a1 * 0.0625f, 4096.f);
    int b2 = q8(v.y - b1 * 0.0625f, 4096.f);
    ((unsigned short*)g_xq1)[row * 128 + t] =
        (unsigned short)((a1 & 0xff) | ((b1 & 0xff) << 8));
    ((unsigned short*)g_xq2)[row * 128 + t] =
        (unsigned short)((a2 & 0xff) | ((b2 & 0xff) << 8));
}

// c: quantization + XLA-order |c|^2 (bit-exact R8 chain).
__global__ void convc_kernel(const float* __restrict__ c) {
    __shared__ float s4[4][4];
    const int t  = threadIdx.x & 127;
    const int rs = threadIdx.x >> 7;
    const int row = blockIdx.x * 4 + rs;
    float2 v = ((const float2*)(c + (size_t)row * D_DIM))[t];
    int a1 = q8(v.x, 16.f), b1 = q8(v.y, 16.f);
    int a2 = q8(v.x - a1 * 0.0625f, 4096.f);
    int b2 = q8(v.y - b1 * 0.0625f, 4096.f);
    ((unsigned short*)g_cq1)[row * 128 + t] =
        (unsigned short)((a1 & 0xff) | ((b1 & 0xff) << 8));
    ((unsigned short*)g_cq2)[row * 128 + t] =
        (unsigned short)((a2 & 0xff) | ((b2 & 0xff) << 8));
    float p = __fmul_rn(v.x, v.x);
    p = __fadd_rn(p, __fmul_rn(v.y, v.y));
#pragma unroll
    for (int off = 16; off; off >>= 1)
        p = __fadd_rn(p, __shfl_down_sync(0xffffffffu, p, off));
    if ((t & 31) == 0) s4[rs][t >> 5] = p;
    __syncthreads();
    if (t == 0)
        g_cnorm[row] = __fadd_rn(__fadd_rn(s4[rs][0], s4[rs][2]),
                                 __fadd_rn(s4[rs][1], s4[rs][3]));
}

__device__ __forceinline__ void top2_update(float& v1, float& v2, int& i1,
                                            float s, int n) {
    if (s < v1)      { v2 = v1; v1 = s; i1 = n; }
    else if (s < v2) { v2 = s; }
}

#define LDSM_X4(R, addr) \
    asm volatile("ldmatrix.sync.aligned.m8n8.x4.shared.b16 {%0,%1,%2,%3}, [%4];" \
        : "=r"((R)[0]), "=r"((R)[1]), "=r"((R)[2]), "=r"((R)[3]) : "r"(addr))

#define IMMA(A, B0, B1, C) \
    asm volatile("mma.sync.aligned.m16n8k32.row.col.s32.s8.s8.s32 " \
        "{%0,%1,%2,%3}, {%4,%5,%6,%7}, {%8,%9}, {%0,%1,%2,%3};" \
        : "+r"((C)[0]), "+r"((C)[1]), "+r"((C)[2]), "+r"((C)[3]) \
        : "r"((A)[0]), "r"((A)[1]), "r"((A)[2]), "r"((A)[3]), "r"(B0), "r"(B1))

// Pass 1: int8 3-term (hh + cross) m16n8k32 MMA GEMM; score = -2*dot + cn.
// CTA: 128 x-rows; 16 n-tiles of 64; warp tile m32 x n32 (8 warps, 4m x 2n).
// smem int8 planes (row stride 80B): xq1@0, xq2@10240, cq1@20480, cq2@25600.
__global__ void __launch_bounds__(256, 2)
vq_pass1(const float* __restrict__ c, float* __restrict__ out)
{
    extern __shared__ char smem[];
    float* cns = (float*)(smem + 30720);   // 1024 f32
    int*   si  = (int*)(smem + 34816);     // 128 int
    float* rv1 = (float*)(smem);           // post-loop aliases
    float* rv2 = (float*)(smem + 1024);
    int*   ri1 = (int*)(smem + 2048);

    const int tid  = threadIdx.x;
    const int lane = tid & 31, warp = tid >> 5;
    const int warp_m = warp & 3, warp_n = warp >> 2;
    const int wm0 = warp_m * 32, wn0 = warp_n * 32;
    const int lrow = lane >> 2, kp = (lane & 3) * 2;
    const long long m0 = (long long)blockIdx.x * 128;

    for (int i = tid; i < K_CENT; i += 256) cns[i] = g_cnorm[i];

    const unsigned sb = (unsigned)__cvta_generic_to_shared(smem);
    unsigned aAddr[2], bAddr[2];
#pragma unroll
    for (int mi = 0; mi < 2; ++mi)
        aAddr[mi] = sb + (wm0 + mi * 16 + (lane & 15)) * 80 + (lane >> 4) * 16;
#pragma unroll
    for (int q = 0; q < 2; ++q)
        bAddr[q] = sb + 20480 + (wn0 + q * 16 + (lane & 15)) * 80 + (lane >> 4) * 16;

    float v1[4], v2[4]; int i1[4];
#pragma unroll
    for (int r = 0; r < 4; ++r) { v1[r] = 3.4e38f; v2[r] = 3.4e38f; i1[r] = 0; }

    for (int n0t = 0; n0t < 16; ++n0t) {
        const int n0 = n0t * 64;
        int hh[2][4][4], cr[2][4][4];
#pragma unroll
        for (int mi = 0; mi < 2; ++mi)
#pragma unroll
            for (int ni = 0; ni < 4; ++ni)
#pragma unroll
                for (int j = 0; j < 4; ++j) { hh[mi][ni][j] = 0; cr[mi][ni][j] = 0; }

        for (int k0 = 0; k0 < D_DIM; k0 += 64) {
            __syncthreads();
            // stage x planes: 128 rows x 64 int8 = 512 uint4 each
#pragma unroll
            for (int it = 0; it < 2; ++it) {
                int idx = it * 256 + tid;
                int m = idx >> 2, u = idx & 3;
                *(uint4*)(smem + m * 80 + u * 16) =
                    *(const uint4*)(g_xq1 + (m0 + m) * D_DIM + k0 + u * 16);
                *(uint4*)(smem + 10240 + m * 80 + u * 16) =
                    *(const uint4*)(g_xq2 + (m0 + m) * D_DIM + k0 + u * 16);
            }
            // stage c planes: 64 rows x 64 int8 = 256 uint4 each
            {
                int n = tid >> 2, u = tid & 3;
                *(uint4*)(smem + 20480 + n * 80 + u * 16) =
                    *(const uint4*)(g_cq1 + (size_t)(n0 + n) * D_DIM + k0 + u * 16);
                *(uint4*)(smem + 25600 + n * 80 + u * 16) =
                    *(const uint4*)(g_cq2 + (size_t)(n0 + n) * D_DIM + k0 + u * 16);
            }
            __syncthreads();

#pragma unroll
            for (int kk = 0; kk < 64; kk += 32) {
                unsigned ah[2][4], al[2][4];
#pragma unroll
                for (int mi = 0; mi < 2; ++mi) {
                    LDSM_X4(ah[mi], aAddr[mi] + kk);
                    LDSM_X4(al[mi], aAddr[mi] + 10240 + kk);
                }
                unsigned bh[2][4], bl[2][4];
#pragma unroll
                for (int q = 0; q < 2; ++q) {
                    LDSM_X4(bh[q], bAddr[q] + kk);
                    LDSM_X4(bl[q], bAddr[q] + 5120 + kk);
                }
#pragma unroll
                for (int mi = 0; mi < 2; ++mi)
#pragma unroll
                    for (int q = 0; q < 2; ++q)
#pragma unroll
                        for (int p = 0; p < 2; ++p) {
                            int ni = q * 2 + p;
                            IMMA(ah[mi], bh[q][p], bh[q][p + 2], hh[mi][ni]);
                            IMMA(al[mi], bh[q][p], bh[q][p + 2], cr[mi][ni]);
                            IMMA(ah[mi], bl[q][p], bl[q][p + 2], cr[mi][ni]);
                        }
            }
        }

        // epilogue: dequant + top-2; n ascending per thread
        const float S1 = -2.0f / 256.0f, S2 = -2.0f / 65536.0f;
#pragma unroll
        for (int ni = 0; ni < 4; ++ni) {
            int n = n0 + wn0 + ni * 8 + kp;
            float cn0 = cns[n], cn1 = cns[n + 1];
#pragma unroll
            for (int mi = 0; mi < 2; ++mi) {
                float s0 = fmaf(S1, (float)hh[mi][ni][0],
                                fmaf(S2, (float)cr[mi][ni][0], cn0));
                float s1 = fmaf(S1, (float)hh[mi][ni][1],
                                fmaf(S2, (float)cr[mi][ni][1], cn1));
                float s2 = fmaf(S1, (float)hh[mi][ni][2],
                                fmaf(S2, (float)cr[mi][ni][2], cn0));
                float s3 = fmaf(S1, (float)hh[mi][ni][3],
                                fmaf(S2, (float)cr[mi][ni][3], cn1));
                top2_update(v1[mi*2],   v2[mi*2],   i1[mi*2],   s0, n);
                top2_update(v1[mi*2],   v2[mi*2],   i1[mi*2],   s1, n + 1);
                top2_update(v1[mi*2+1], v2[mi*2+1], i1[mi*2+1], s2, n);
                top2_update(v1[mi*2+1], v2[mi*2+1], i1[mi*2+1], s3, n + 1);
            }
        }
    }

    // quad reduce (lanes 4q..4q+3 share rows)
#pragma unroll
    for (int off = 1; off <= 2; off <<= 1) {
#pragma unroll
        for (int rp = 0; rp < 4; ++rp) {
            float ov1 = __shfl_xor_sync(0xffffffffu, v1[rp], off);
            int   oi1 = __shfl_xor_sync(0xffffffffu, i1[rp], off);
            float ov2 = __shfl_xor_sync(0xffffffffu, v2[rp], off);
            if (ov1 < v1[rp] || (ov1 == v1[rp] && oi1 < i1[rp])) {
                v2[rp] = fminf(v1[rp], ov2);
                v1[rp] = ov1; i1[rp] = oi1;
            } else {
                v2[rp] = fminf(v2[rp], ov1);
            }
        }
    }

    __syncthreads();
    if ((lane & 3) == 0) {
#pragma unroll
        for (int rp = 0; rp < 4; ++rp) {
            int row = wm0 + (rp >> 1) * 16 + (rp & 1) * 8 + lrow;
            rv1[row * 2 + warp_n] = v1[rp];
            rv2[row * 2 + warp_n] = v2[rp];
            ri1[row * 2 + warp_n] = i1[rp];
        }
    }
    __syncthreads();

    if (tid < 128) {
        float a1 = rv1[tid * 2], a2 = rv2[tid * 2];
        int   ai = ri1[tid * 2];
        float b1 = rv1[tid * 2 + 1], b2 = rv2[tid * 2 + 1];
        int   bi = ri1[tid * 2 + 1];
        float fv1, fv2; int fi;
        if (a1 < b1 || (a1 == b1 && ai < bi)) {
            fv1 = a1; fi = ai; fv2 = fminf(a2, b1);
        } else {
            fv1 = b1; fi = bi; fv2 = fminf(b2, a1);
        }
        si[tid] = fi;
        if (fv2 - fv1 < MARGIN) {
            int p = atomicAdd(&g_count, 1);
            g_amb[p] = (int)(m0 + tid);
        }
    }
    __syncthreads();

    {
        int rr = tid >> 1, half = tid & 1;
        int bi = si[rr];
        const float4* src = (const float4*)(c + (size_t)bi * D_DIM) + half * 32;
        float4*       dst = (float4*)(out + (m0 + rr) * D_DIM) + half * 32;
#pragma unroll
        for (int q = 0; q < 32; ++q) dst[q] = src[q];
    }
}

// Rescore: 4 ambiguous rows per block (c tiles shared). Exact R8 chain:
// XLA-order xn; ascending-k=256 single-accumulator FFMA per centroid;
// score fl(fl(-2*dot+xn)+cn); first-index argmin.
__global__ void __launch_bounds__(128)
vq_rescore(const float* __restrict__ x, const float* __restrict__ c,
           float* __restrict__ out)
{
    extern __shared__ float sm[];
    float* xrow = sm;                     // [4][256]
    float* cs   = sm + 1024;              // [64][129]
    float* rv   = sm + 1024 + 8256;       // [128]
    int*   ri   = (int*)(rv + 128);       // [128]
    int*   rows = (int*)(ri + 128);       // [4]
    int*   fi   = rows + 4;               // [4]
    float* xn_s = (float*)(fi + 4);       // [4]
    float* s4   = xn_s + 4;               // [4]

    const int t = threadIdx.x;
    const int count = g_count;
    const int ntiles = (count + 3) >> 2;

    for (int tile = blockIdx.x; tile < ntiles; tile += gridDim.x) {
        if (t < 4) {
            int gi = tile * 4 + t; if (gi > count - 1) gi = count - 1;
            rows[t] = g_amb[gi];
        }
        __syncthreads();

        // stage 4 x rows + XLA-order |x|^2 each
        for (int r = 0; r < 4; ++r) {
            float2 v = ((const float2*)(x + (size_t)rows[r] * D_DIM))[t];
            ((float2*)(xrow + r * 256))[t] = v;
            float p = __fmul_rn(v.x, v.x);
            p = __fadd_rn(p, __fmul_rn(v.y, v.y));
#pragma unroll
            for (int off = 16; off; off >>= 1)
                p = __fadd_rn(p, __shfl_down_sync(0xffffffffu, p, off));
            if ((t & 31) == 0) s4[t >> 5] = p;
            __syncthreads();
            if (t == 0)
                xn_s[r] = __fadd_rn(__fadd_rn(s4[0], s4[2]),
                                    __fadd_rn(s4[1], s4[3]));
            __syncthreads();
        }

        float bestv[4]; int besti[4];
#pragma unroll
        for (int r = 0; r < 4; ++r) { bestv[r] = 3.4e38f; besti[r] = 0; }

        for (int n0 = 0; n0 < K_CENT; n0 += 128) {
            float acc[4] = {0.f, 0.f, 0.f, 0.f};   // thread owns centroid n0+t
            for (int k0 = 0; k0 < D_DIM; k0 += 64) {
                __syncthreads();
#pragma unroll
                for (int it = 0; it < 16; ++it) {
                    int idx = it * 128 + t;
                    int n = idx >> 4, f4 = idx & 15;
                    float4 cv = ((const float4*)(c + (size_t)(n0 + n) * D_DIM + k0))[f4];
                    int kk = f4 * 4;
                    cs[(kk + 0) * 129 + n] = cv.x;
                    cs[(kk + 1) * 129 + n] = cv.y;
                    cs[(kk + 2) * 129 + n] = cv.z;
                    cs[(kk + 3) * 129 + n] = cv.w;
                }
                __syncthreads();
#pragma unroll 8
                for (int k = 0; k < 64; ++k) {
                    float cv = cs[k * 129 + t];
#pragma unroll
                    for (int r = 0; r < 4; ++r)
                        acc[r] = __fmaf_rn(xrow[r * 256 + k0 + k], cv, acc[r]);
                }
            }
            float cn = g_cnorm[n0 + t];
#pragma unroll
            for (int r = 0; r < 4; ++r) {
                float s = __fadd_rn(__fadd_rn(__fmul_rn(-2.0f, acc[r]),
                                              xn_s[r]), cn);
                if (s < bestv[r]) { bestv[r] = s; besti[r] = n0 + t; }
            }
        }

        // per-row tree reduce with first-index tie-break
        for (int r = 0; r < 4; ++r) {
            rv[t] = bestv[r]; ri[t] = besti[r];
            __syncthreads();
            for (int o = 64; o; o >>= 1) {
                if (t < o) {
                    float ov = rv[t + o]; int oi = ri[t + o];
                    if (ov < rv[t] || (ov == rv[t] && oi < ri[t])) {
                        rv[t] = ov; ri[t] = oi;
                    }
                }
                __syncthreads();
            }
            if (t == 0) fi[r] = ri[0];
            __syncthreads();
        }

        // write 4 rows: 256 float4 total, 2 per thread
#pragma unroll
        for (int it = 0; it < 2; ++it) {
            int idx = it * 128 + t;
            int r = idx >> 6, q = idx & 63;
            const float4* src = (const float4*)(c + (size_t)fi[r] * D_DIM);
            float4*       dst = (float4*)(out + (size_t)rows[r] * D_DIM);
            dst[q] = src[q];
        }
        __syncthreads();
    }
}

extern "C" void kernel_launch(void* const* d_in, const int* in_sizes, int n_in,
                              void* d_out, int out_size) {
    const float* x = (const float*)d_in[0];
    const float* c = (const float*)d_in[1];
    float* out = (float*)d_out;
    int N = in_sizes[0] / D_DIM;   // 131072
    int K = in_sizes[1] / D_DIM;   // 1024

    zero_kernel<<<1, 32>>>();
    convx_kernel<<<N / 4, 512>>>(x);
    convc_kernel<<<K / 4, 512>>>(c);
    vq_pass1<<<N / 128, 256, 35840>>>(c, out);
    vq_rescore<<<256, 128, 38400>>>(x, c, out);
}

// round 17
// speedup vs baseline: 2.0265x; 1.8233x over previous
#include <cuda_runtime.h>
#include <cuda_bf16.h>

#define D_DIM   256
#define K_CENT  1024
#define N_MAX   131072
#define MARGIN  2e-3f

__device__ float g_cnorm[K_CENT];
__device__ int   g_amb[N_MAX];
__device__ int   g_count;
__device__ __align__(16) __nv_bfloat16 g_xh[(size_t)N_MAX * D_DIM];  // 64 MB
__device__ __align__(16) __nv_bfloat16 g_xl[(size_t)N_MAX * D_DIM];  // 64 MB
__device__ __align__(16) __nv_bfloat16 g_ch[K_CENT * D_DIM];
__device__ __align__(16) __nv_bfloat16 g_cl[K_CENT * D_DIM];

__global__ void zero_kernel() { if (threadIdx.x == 0) g_count = 0; }

// Split fp32 row into bf16 hi + lo planes. 4 rows / 512-thread block.
__global__ void convx_kernel(const float* __restrict__ x) {
    const int t  = threadIdx.x & 127;
    const int rs = threadIdx.x >> 7;
    const size_t row = (size_t)blockIdx.x * 4 + rs;
    float2 v = ((const float2*)(x + row * D_DIM))[t];
    __nv_bfloat162 h = __floats2bfloat162_rn(v.x, v.y);
    __nv_bfloat162 l = __floats2bfloat162_rn(v.x - __bfloat162float(h.x),
                                             v.y - __bfloat162float(h.y));
    ((__nv_bfloat162*)g_xh)[row * 128 + t] = h;
    ((__nv_bfloat162*)g_xl)[row * 128 + t] = l;
}

// c: bf16 hi/lo split + XLA-order |c|^2 (bit-exact R8 chain).
__global__ void convc_kernel(const float* __restrict__ c) {
    __shared__ float s4[4][4];
    const int t  = threadIdx.x & 127;
    const int rs = threadIdx.x >> 7;
    const int row = blockIdx.x * 4 + rs;
    float2 v = ((const float2*)(c + (size_t)row * D_DIM))[t];
    __nv_bfloat162 h = __floats2bfloat162_rn(v.x, v.y);
    __nv_bfloat162 l = __floats2bfloat162_rn(v.x - __bfloat162float(h.x),
                                             v.y - __bfloat162float(h.y));
    ((__nv_bfloat162*)g_ch)[row * 128 + t] = h;
    ((__nv_bfloat162*)g_cl)[row * 128 + t] = l;
    float p = __fmul_rn(v.x, v.x);
    p = __fadd_rn(p, __fmul_rn(v.y, v.y));
#pragma unroll
    for (int off = 16; off; off >>= 1)
        p = __fadd_rn(p, __shfl_down_sync(0xffffffffu, p, off));
    if ((t & 31) == 0) s4[rs][t >> 5] = p;
    __syncthreads();
    if (t == 0)
        g_cnorm[row] = __fadd_rn(__fadd_rn(s4[rs][0], s4[rs][2]),
                                 __fadd_rn(s4[rs][1], s4[rs][3]));
}

__device__ __forceinline__ void top2_update(float& v1, float& v2, int& i1,
                                            float s, int n) {
    if (s < v1)      { v2 = v1; v1 = s; i1 = n; }
    else if (s < v2) { v2 = s; }
}

#define LDSM_X4(R, addr) \
    asm volatile("ldmatrix.sync.aligned.m8n8.x4.shared.b16 {%0,%1,%2,%3}, [%4];" \
        : "=r"((R)[0]), "=r"((R)[1]), "=r"((R)[2]), "=r"((R)[3]) : "r"(addr))

#define MMA16816(A, B0, B1, C) \
    asm volatile("mma.sync.aligned.m16n8k16.row.col.f32.bf16.bf16.f32 " \
        "{%0,%1,%2,%3}, {%4,%5,%6,%7}, {%8,%9}, {%0,%1,%2,%3};" \
        : "+f"((C)[0]), "+f"((C)[1]), "+f"((C)[2]), "+f"((C)[3]) \
        : "r"((A)[0]), "r"((A)[1]), "r"((A)[2]), "r"((A)[3]), "r"(B0), "r"(B1))

__device__ __forceinline__ void cp16(unsigned dst, const void* src) {
    asm volatile("cp.async.cg.shared.global [%0], [%1], 16;"
                 :: "r"(dst), "l"(src));
}
#define CP_COMMIT() asm volatile("cp.async.commit_group;" ::: "memory")
#define CP_WAIT(n)  asm volatile("cp.async.wait_group %0;" :: "n"(n) : "memory")

// Pass 1: split-bf16 (hh+lh+hl) mma.sync GEMM with cp.async double-buffered
// k16 chunks. CTA: 128 x-rows x 1024 centroids; warp tile m32 x n64.
// smem: 2 buffers x 24576B; per buffer (48B row stride, 16 bf16 used):
//   xh@0, xl@6144, ch@12288, cl@18432.  Total 49152B dynamic.
// B ldmatrix layout => matrices (n-lo,k-lo),(n-lo,k-hi),(n-hi,k-lo),(n-hi,k-hi);
// MMA pairing is bh[2p], bh[2p+1]  (the R13-validated pairing).
__global__ void __launch_bounds__(256, 2)
vq_pass1(const float* __restrict__ c, float* __restrict__ out)
{
    extern __shared__ char smem[];
    float* rv1 = (float*)(smem);            // post-loop aliases
    float* rv2 = (float*)(smem + 1024);
    int*   ri1 = (int*)(smem + 2048);
    int*   si  = (int*)(smem + 3072);

    const int tid  = threadIdx.x;
    const int lane = tid & 31, warp = tid >> 5;
    const int warp_m = warp & 3, warp_n = warp >> 2;
    const int wm0 = warp_m * 32, wn0 = warp_n * 64;
    const int lrow = lane >> 2, kp = (lane & 3) * 2;
    const long long m0 = (long long)blockIdx.x * 128;

    const unsigned sb = (unsigned)__cvta_generic_to_shared(smem);
    unsigned aOff[2], bOff[4];
#pragma unroll
    for (int mi = 0; mi < 2; ++mi)
        aOff[mi] = (wm0 + mi * 16 + (lane & 15)) * 48 + (lane >> 4) * 16;
#pragma unroll
    for (int q = 0; q < 4; ++q)
        bOff[q] = 12288u +
                  (wn0 + q * 16 + ((lane >> 4) & 1) * 8 + (lane & 7)) * 48 +
                  ((lane >> 3) & 1) * 16;

    const int prow = tid >> 1, phalf = tid & 1;   // prefetch mapping

    float v1[4], v2[4]; int i1[4];
#pragma unroll
    for (int r = 0; r < 4; ++r) { v1[r] = 3.4e38f; v2[r] = 3.4e38f; i1[r] = 0; }

    for (int n0t = 0; n0t < 8; ++n0t) {
        const int n0 = n0t * 128;
        float acc[2][8][4];
#pragma unroll
        for (int mi = 0; mi < 2; ++mi)
#pragma unroll
            for (int ni = 0; ni < 8; ++ni)
#pragma unroll
                for (int j = 0; j < 4; ++j) acc[mi][ni][j] = 0.f;

        // prefetch chunk 0 into buffer 0
        {
            unsigned dst = sb + prow * 48 + phalf * 16;
            cp16(dst,          g_xh + (m0 + prow) * D_DIM + phalf * 8);
            cp16(dst + 6144,   g_xl + (m0 + prow) * D_DIM + phalf * 8);
            cp16(dst + 12288,  g_ch + (size_t)(n0 + prow) * D_DIM + phalf * 8);
            cp16(dst + 18432,  g_cl + (size_t)(n0 + prow) * D_DIM + phalf * 8);
            CP_COMMIT();
        }

        for (int ch = 0; ch < 16; ++ch) {
            if (ch < 15) {
                const int k0 = (ch + 1) * 16;
                unsigned dst = sb + ((ch + 1) & 1) * 24576u + prow * 48 + phalf * 16;
                cp16(dst,          g_xh + (m0 + prow) * D_DIM + k0 + phalf * 8);
                cp16(dst + 6144,   g_xl + (m0 + prow) * D_DIM + k0 + phalf * 8);
                cp16(dst + 12288,  g_ch + (size_t)(n0 + prow) * D_DIM + k0 + phalf * 8);
                cp16(dst + 18432,  g_cl + (size_t)(n0 + prow) * D_DIM + k0 + phalf * 8);
                CP_COMMIT();
                CP_WAIT(1);
            } else {
                CP_WAIT(0);
            }
            __syncthreads();

            const unsigned bufb = sb + (ch & 1) * 24576u;
            unsigned ah[2][4], al[2][4];
#pragma unroll
            for (int mi = 0; mi < 2; ++mi) {
                LDSM_X4(ah[mi], bufb + aOff[mi]);
                LDSM_X4(al[mi], bufb + aOff[mi] + 6144);
            }
            unsigned bh[4][4], bl[4][4];
#pragma unroll
            for (int q = 0; q < 4; ++q) {
                LDSM_X4(bh[q], bufb + bOff[q]);
                LDSM_X4(bl[q], bufb + bOff[q] + 6144);
            }
#pragma unroll
            for (int mi = 0; mi < 2; ++mi)
#pragma unroll
                for (int q = 0; q < 4; ++q)
#pragma unroll
                    for (int p = 0; p < 2; ++p) {
                        int ni = q * 2 + p;
                        MMA16816(ah[mi], bh[q][2*p], bh[q][2*p+1], acc[mi][ni]);
                        MMA16816(al[mi], bh[q][2*p], bh[q][2*p+1], acc[mi][ni]);
                        MMA16816(ah[mi], bl[q][2*p], bl[q][2*p+1], acc[mi][ni]);
                    }
            __syncthreads();
        }

        // epilogue: scores, n ascending per thread; cnorm via LDG (L2 hit)
#pragma unroll
        for (int ni = 0; ni < 8; ++ni) {
            int n = n0 + wn0 + ni * 8 + kp;
            float2 cn = *(const float2*)(g_cnorm + n);
#pragma unroll
            for (int mi = 0; mi < 2; ++mi) {
                top2_update(v1[mi*2],   v2[mi*2],   i1[mi*2],
                            fmaf(-2.f, acc[mi][ni][0], cn.x), n);
                top2_update(v1[mi*2],   v2[mi*2],   i1[mi*2],
                            fmaf(-2.f, acc[mi][ni][1], cn.y), n + 1);
                top2_update(v1[mi*2+1], v2[mi*2+1], i1[mi*2+1],
                            fmaf(-2.f, acc[mi][ni][2], cn.x), n);
                top2_update(v1[mi*2+1], v2[mi*2+1], i1[mi*2+1],
                            fmaf(-2.f, acc[mi][ni][3], cn.y), n + 1);
            }
        }
    }

    // quad reduce (lanes 4q..4q+3 share the same 4 rows)
#pragma unroll
    for (int off = 1; off <= 2; off <<= 1) {
#pragma unroll
        for (int rp = 0; rp < 4; ++rp) {
            float ov1 = __shfl_xor_sync(0xffffffffu, v1[rp], off);
            int   oi1 = __shfl_xor_sync(0xffffffffu, i1[rp], off);
            float ov2 = __shfl_xor_sync(0xffffffffu, v2[rp], off);
            if (ov1 < v1[rp] || (ov1 == v1[rp] && oi1 < i1[rp])) {
                v2[rp] = fminf(v1[rp], ov2);
                v1[rp] = ov1; i1[rp] = oi1;
            } else {
                v2[rp] = fminf(v2[rp], ov1);
            }
        }
    }

    __syncthreads();   // buffers dead; alias reduce arrays
    if ((lane & 3) == 0) {
#pragma unroll
        for (int rp = 0; rp < 4; ++rp) {
            int row = wm0 + (rp >> 1) * 16 + (rp & 1) * 8 + lrow;
            rv1[row * 2 + warp_n] = v1[rp];
            rv2[row * 2 + warp_n] = v2[rp];
            ri1[row * 2 + warp_n] = i1[rp];
        }
    }
    __syncthreads();

    if (tid < 128) {
        float a1 = rv1[tid * 2], a2 = rv2[tid * 2];
        int   ai = ri1[tid * 2];
        float b1 = rv1[tid * 2 + 1], b2 = rv2[tid * 2 + 1];
        int   bi = ri1[tid * 2 + 1];
        float fv1, fv2; int fi;
        if (a1 < b1 || (a1 == b1 && ai < bi)) {
            fv1 = a1; fi = ai; fv2 = fminf(a2, b1);
        } else {
            fv1 = b1; fi = bi; fv2 = fminf(b2, a1);
        }
        si[tid] = fi;
        if (fv2 - fv1 < MARGIN) {
            int p = atomicAdd(&g_count, 1);
            g_amb[p] = (int)(m0 + tid);
        }
    }
    __syncthreads();

    // fused gather (fp32 centroids): 2 threads per row
    {
        int rr = tid >> 1, half = tid & 1;
        int bi = si[rr];
        const float4* src = (const float4*)(c + (size_t)bi * D_DIM) + half * 32;
        float4*       dst = (float4*)(out + (m0 + rr) * D_DIM) + half * 32;
#pragma unroll
        for (int q = 0; q < 32; ++q) dst[q] = src[q];
    }
}

// Rescore: 4 ambiguous rows per block (c tiles shared). Exact R8 chain:
// XLA-order xn; ascending-k=256 single-accumulator FFMA per centroid;
// score fl(fl(-2*dot+xn)+cn); first-index argmin.
__global__ void __launch_bounds__(128)
vq_rescore(const float* __restrict__ x, const float* __restrict__ c,
           float* __restrict__ out)
{
    extern __shared__ float sm[];
    float* xrow = sm;                     // [4][256]
    float* cs   = sm + 1024;              // [64][129]
    float* rv   = sm + 1024 + 8256;       // [128]
    int*   ri   = (int*)(rv + 128);       // [128]
    int*   rows = (int*)(ri + 128);       // [4]
    int*   fi   = rows + 4;               // [4]
    float* xn_s = (float*)(fi + 4);       // [4]
    float* s4   = xn_s + 4;               // [4]

    const int t = threadIdx.x;
    const int count = g_count;
    const int ntiles = (count + 3) >> 2;

    for (int tile = blockIdx.x; tile < ntiles; tile += gridDim.x) {
        if (t < 4) {
            int gi = tile * 4 + t; if (gi > count - 1) gi = count - 1;
            rows[t] = g_amb[gi];
        }
        __syncthreads();

        for (int r = 0; r < 4; ++r) {
            float2 v = ((const float2*)(x + (size_t)rows[r] * D_DIM))[t];
            ((float2*)(xrow + r * 256))[t] = v;
            float p = __fmul_rn(v.x, v.x);
            p = __fadd_rn(p, __fmul_rn(v.y, v.y));
#pragma unroll
            for (int off = 16; off; off >>= 1)
                p = __fadd_rn(p, __shfl_down_sync(0xffffffffu, p, off));
            if ((t & 31) == 0) s4[t >> 5] = p;
            __syncthreads();
            if (t == 0)
                xn_s[r] = __fadd_rn(__fadd_rn(s4[0], s4[2]),
                                    __fadd_rn(s4[1], s4[3]));
            __syncthreads();
        }

        float bestv[4]; int besti[4];
#pragma unroll
        for (int r = 0; r < 4; ++r) { bestv[r] = 3.4e38f; besti[r] = 0; }

        for (int n0 = 0; n0 < K_CENT; n0 += 128) {
            float acc[4] = {0.f, 0.f, 0.f, 0.f};
            for (int k0 = 0; k0 < D_DIM; k0 += 64) {
                __syncthreads();
#pragma unroll
                for (int it = 0; it < 16; ++it) {
                    int idx = it * 128 + t;
                    int n = idx >> 4, f4 = idx & 15;
                    float4 cv = ((const float4*)(c + (size_t)(n0 + n) * D_DIM + k0))[f4];
                    int kk = f4 * 4;
                    cs[(kk + 0) * 129 + n] = cv.x;
                    cs[(kk + 1) * 129 + n] = cv.y;
                    cs[(kk + 2) * 129 + n] = cv.z;
                    cs[(kk + 3) * 129 + n] = cv.w;
                }
                __syncthreads();
#pragma unroll 8
                for (int k = 0; k < 64; ++k) {
                    float cv = cs[k * 129 + t];
#pragma unroll
                    for (int r = 0; r < 4; ++r)
                        acc[r] = __fmaf_rn(xrow[r * 256 + k0 + k], cv, acc[r]);
                }
            }
            float cn = g_cnorm[n0 + t];
#pragma unroll
            for (int r = 0; r < 4; ++r) {
                float s = __fadd_rn(__fadd_rn(__fmul_rn(-2.0f, acc[r]),
                                              xn_s[r]), cn);
                if (s < bestv[r]) { bestv[r] = s; besti[r] = n0 + t; }
            }
        }

        for (int r = 0; r < 4; ++r) {
            rv[t] = bestv[r]; ri[t] = besti[r];
            __syncthreads();
            for (int o = 64; o; o >>= 1) {
                if (t < o) {
                    float ov = rv[t + o]; int oi = ri[t + o];
                    if (ov < rv[t] || (ov == rv[t] && oi < ri[t])) {
                        rv[t] = ov; ri[t] = oi;
                    }
                }
                __syncthreads();
            }
            if (t == 0) fi[r] = ri[0];
            __syncthreads();
        }

#pragma unroll
        for (int it = 0; it < 2; ++it) {
            int idx = it * 128 + t;
            int r = idx >> 6, q = idx & 63;
            const float4* src = (const float4*)(c + (size_t)fi[r] * D_DIM);
            float4*       dst = (float4*)(out + (size_t)rows[r] * D_DIM);
            dst[q] = src[q];
        }
        __syncthreads();
    }
}

extern "C" void kernel_launch(void* const* d_in, const int* in_sizes, int n_in,
                              void* d_out, int out_size) {
    const float* x = (const float*)d_in[0];
    const float* c = (const float*)d_in[1];
    float* out = (float*)d_out;
    int N = in_sizes[0] / D_DIM;   // 131072
    int K = in_sizes[1] / D_DIM;   // 1024

    zero_kernel<<<1, 32>>>();
    convx_kernel<<<N / 4, 512>>>(x);
    convc_kernel<<<K / 4, 512>>>(c);
    vq_pass1<<<N / 128, 256, 49152>>>(c, out);
    vq_rescore<<<256, 128, 38400>>>(x, c, out);
}